// round 1
// baseline (speedup 1.0000x reference)
#include <cuda_runtime.h>
#include <cstdint>

// LSTM: IN=14, H=28, OUT=2, B=4096, T=512
// One warp per sequence. Lane j (0..27) owns hidden unit j: its 4 gate rows of
// W_ih (4x14) and W_hh (4x28) live in registers as f32x2 pairs (even/odd k).
// Per step: gates via packed fma.rn.f32x2 (2 MACs/issue), h broadcast via smem,
// x prefetched one step ahead. Activations via ex2.approx+rcp.approx (~1e-7 rel).

#define IN_DIM 14
#define HID    28
#define TSTEPS 512
#define BATCH  4096

typedef unsigned long long u64;

__device__ __forceinline__ u64 pack2(float lo, float hi) {
    u64 r; asm("mov.b64 %0, {%1, %2};" : "=l"(r) : "f"(lo), "f"(hi)); return r;
}
__device__ __forceinline__ void unpack2(u64 v, float& lo, float& hi) {
    asm("mov.b64 {%0, %1}, %2;" : "=f"(lo), "=f"(hi) : "l"(v));
}
__device__ __forceinline__ void ffma2(u64& acc, u64 a, u64 b) {
    asm("fma.rn.f32x2 %0, %1, %2, %0;" : "+l"(acc) : "l"(a), "l"(b));
}
__device__ __forceinline__ float fast_ex2(float x) {
    float r; asm("ex2.approx.f32 %0, %1;" : "=f"(r) : "f"(x)); return r;
}
__device__ __forceinline__ float fast_rcp(float x) {
    float r; asm("rcp.approx.f32 %0, %1;" : "=f"(r) : "f"(x)); return r;
}
// sigmoid(x) = 1 / (1 + 2^(-x*log2e))
__device__ __forceinline__ float sigm(float x) {
    return fast_rcp(fmaf(0.0f, x, 1.0f) + fast_ex2(-1.4426950408889634f * x));
}
// tanh(x) = 2*sigmoid(2x) - 1
__device__ __forceinline__ float tanh_f(float x) {
    return fmaf(2.0f, fast_rcp(1.0f + fast_ex2(-2.8853900817779268f * x)), -1.0f);
}

__global__ void __launch_bounds__(32)
lstm_kernel(const float* __restrict__ x,
            const float* __restrict__ W_ih,
            const float* __restrict__ W_hh,
            const float* __restrict__ b_ih,
            const float* __restrict__ b_hh,
            const float* __restrict__ W_out,
            const float* __restrict__ b_out,
            float* __restrict__ out)
{
    const int seq  = blockIdx.x;            // 4096 blocks = 4096 sequences
    const int lane = threadIdx.x;           // 32 threads = 1 warp
    const int j    = (lane < HID) ? lane : (HID - 1);  // lanes 28..31 mirror lane 27

    // ---- register-resident weights (f32x2 pairs over k) ----
    u64 wih[4][IN_DIM / 2];   // 4 gates x 7 pairs
    u64 whh[4][HID / 2];      // 4 gates x 14 pairs
    float bias[4];
#pragma unroll
    for (int g = 0; g < 4; g++) {
        const int r = g * HID + j;
        const u64* wi = (const u64*)(W_ih + r * IN_DIM);   // 56B row -> 8B aligned
#pragma unroll
        for (int p = 0; p < IN_DIM / 2; p++) wih[g][p] = wi[p];
        const u64* wh = (const u64*)(W_hh + r * HID);      // 112B row -> 8B aligned
#pragma unroll
        for (int p = 0; p < HID / 2; p++) whh[g][p] = wh[p];
        bias[g] = b_ih[r] + b_hh[r];
    }

    __shared__ __align__(16) float hs[32];
    hs[lane] = 0.0f;
    float h = 0.0f, c = 0.0f;
    __syncwarp();

    // x for this sequence is exactly 512*7 contiguous u64 pairs
    const u64* xq = (const u64*)(x + (size_t)seq * TSTEPS * IN_DIM);
    u64 xc[7];
#pragma unroll
    for (int p = 0; p < 7; p++) xc[p] = xq[p];

#pragma unroll 1
    for (int t = 0; t < TSTEPS; t++) {
        // prefetch next step's x (uniform-address LDG.64, HBM latency hidden)
        u64 xn[7];
        if (t + 1 < TSTEPS) {
            const u64* xr = xq + (t + 1) * 7;
#pragma unroll
            for (int p = 0; p < 7; p++) xn[p] = xr[p];
        }

        // packed accumulators: lo half = even-k partials (+bias), hi = odd-k
        u64 a0 = pack2(bias[0], 0.0f);
        u64 a1 = pack2(bias[1], 0.0f);
        u64 a2 = pack2(bias[2], 0.0f);
        u64 a3 = pack2(bias[3], 0.0f);

        // x part: 7 pairs x 4 gates = 28 FFMA2
#pragma unroll
        for (int p = 0; p < 7; p++) {
            ffma2(a0, wih[0][p], xc[p]);
            ffma2(a1, wih[1][p], xc[p]);
            ffma2(a2, wih[2][p], xc[p]);
            ffma2(a3, wih[3][p], xc[p]);
        }

        // h part: 14 pairs broadcast from smem x 4 gates = 56 FFMA2
#pragma unroll
        for (int q = 0; q < HID / 2; q++) {
            u64 hv = *(const u64*)(hs + 2 * q);   // LDS.64 broadcast, conflict-free
            ffma2(a0, whh[0][q], hv);
            ffma2(a1, whh[1][q], hv);
            ffma2(a2, whh[2][q], hv);
            ffma2(a3, whh[3][q], hv);
        }

        float lo, hi;
        unpack2(a0, lo, hi); const float gi = lo + hi;
        unpack2(a1, lo, hi); const float gf = lo + hi;
        unpack2(a2, lo, hi); const float gg = lo + hi;
        unpack2(a3, lo, hi); const float go = lo + hi;

        const float ia = sigm(gi);
        const float fa = sigm(gf);
        const float ga = tanh_f(gg);
        const float oa = sigm(go);
        c = fmaf(fa, c, ia * ga);
        h = oa * tanh_f(c);

        __syncwarp();            // all lanes done reading prev h
        hs[lane] = h;
        __syncwarp();            // new h visible

#pragma unroll
        for (int p = 0; p < 7; p++) xc[p] = xn[p];
    }

    // out[seq, o] = sum_j h_j * W_out[o, j] + b_out[o]
    const float w0 = (lane < HID) ? W_out[j]       : 0.0f;
    const float w1 = (lane < HID) ? W_out[HID + j] : 0.0f;
    float v0 = h * w0;
    float v1 = h * w1;
#pragma unroll
    for (int off = 16; off; off >>= 1) {
        v0 += __shfl_down_sync(0xffffffffu, v0, off);
        v1 += __shfl_down_sync(0xffffffffu, v1, off);
    }
    if (lane == 0) {
        out[seq * 2 + 0] = v0 + b_out[0];
        out[seq * 2 + 1] = v1 + b_out[1];
    }
}

extern "C" void kernel_launch(void* const* d_in, const int* in_sizes, int n_in,
                              void* d_out, int out_size)
{
    const float* x     = (const float*)d_in[0];
    const float* W_ih  = (const float*)d_in[1];
    const float* W_hh  = (const float*)d_in[2];
    const float* b_ih  = (const float*)d_in[3];
    const float* b_hh  = (const float*)d_in[4];
    const float* W_out = (const float*)d_in[5];
    const float* b_out = (const float*)d_in[6];
    float* out = (float*)d_out;

    lstm_kernel<<<BATCH, 32>>>(x, W_ih, W_hh, b_ih, b_hh, W_out, b_out, out);
}